// round 7
// baseline (speedup 1.0000x reference)
#include <cuda_runtime.h>
#include <cuda_fp16.h>
#include <stdint.h>

#define Bn    4
#define Nn    2048
#define HEADSn 8
#define DHn   64
#define HIDn  512
#define L2E   1.4426950408889634f
#define QSCALEC (0.125f * 1.4426950408889634f)

// Scratch (device globals; allocation-free rule)
__device__ __half g_xh   [Bn * Nn * 512];
__device__ __half g_wqkvh[512 * 1536];
__device__ __half g_wouth[512 * 512];
__device__ __half g_qkvh [Bn * Nn * 1536];   // q|k|v halves (q pre-scaled)
__device__ __half g_oh   [Bn * Nn * 512];
__device__ int    g_focus[Bn];

// ---------------------------------------------------------------------------
__device__ __forceinline__ float ex2f(float x) {
    float r; asm("ex2.approx.ftz.f32 %0, %1;" : "=f"(r) : "f"(x)); return r;
}
__device__ __forceinline__ uint32_t ex2h2(float a, float b) {
    __half2 h = __floats2half2_rn(a, b);
    uint32_t u = *reinterpret_cast<uint32_t*>(&h);
    asm("ex2.approx.f16x2 %0, %0;" : "+r"(u));
    return u;
}
__device__ __forceinline__ uint32_t packf2(float a, float b) {
    __half2 h = __floats2half2_rn(a, b);
    return *reinterpret_cast<uint32_t*>(&h);
}
__device__ __forceinline__ void mma16(float* d, const uint32_t* a, uint32_t b0, uint32_t b1) {
    asm volatile(
        "mma.sync.aligned.m16n8k16.row.col.f32.f16.f16.f32 "
        "{%0,%1,%2,%3}, {%4,%5,%6,%7}, {%8,%9}, {%0,%1,%2,%3};"
        : "+f"(d[0]), "+f"(d[1]), "+f"(d[2]), "+f"(d[3])
        : "r"(a[0]), "r"(a[1]), "r"(a[2]), "r"(a[3]), "r"(b0), "r"(b1));
}
__device__ __forceinline__ void ldsm4(uint32_t& r0, uint32_t& r1, uint32_t& r2, uint32_t& r3,
                                      uint32_t a) {
    asm volatile("ldmatrix.sync.aligned.m8n8.x4.shared.b16 {%0,%1,%2,%3}, [%4];"
        : "=r"(r0), "=r"(r1), "=r"(r2), "=r"(r3) : "r"(a));
}
__device__ __forceinline__ void ldsm4t(uint32_t& r0, uint32_t& r1, uint32_t& r2, uint32_t& r3,
                                       uint32_t a) {
    asm volatile("ldmatrix.sync.aligned.m8n8.x4.trans.shared.b16 {%0,%1,%2,%3}, [%4];"
        : "=r"(r0), "=r"(r1), "=r"(r2), "=r"(r3) : "r"(a));
}
__device__ __forceinline__ void ldsm2t(uint32_t& r0, uint32_t& r1, uint32_t a) {
    asm volatile("ldmatrix.sync.aligned.m8n8.x2.trans.shared.b16 {%0,%1}, [%2];"
        : "=r"(r0), "=r"(r1) : "r"(a));
}
__device__ __forceinline__ void cpa16(void* s, const void* g) {
    uint32_t sa = (uint32_t)__cvta_generic_to_shared(s);
    asm volatile("cp.async.ca.shared.global [%0], [%1], 16;" :: "r"(sa), "l"(g));
}
#define CP_COMMIT() asm volatile("cp.async.commit_group;")
#define CP_WAIT1()  asm volatile("cp.async.wait_group 1;")

// ---------------------------------------------------------------------------
__global__ void decode_mask_kernel(const unsigned char* __restrict__ p) {
    unsigned int w[4];
#pragma unroll
    for (int i = 0; i < 4; i++) w[i] = ((const unsigned int*)p)[i];
    bool allF = true, allI = true, anyNZ = false;
#pragma unroll
    for (int i = 0; i < 4; i++) {
        if (w[i] != 0u) anyNZ = true;
        if (w[i] != 0u && w[i] != 0x3F800000u) allF = false;
        if (w[i] > 1u) allI = false;
    }
    if (anyNZ && allF)      for (int i = 0; i < 4; i++) g_focus[i] = (w[i] == 0x3F800000u);
    else if (allI)          for (int i = 0; i < 4; i++) g_focus[i] = (int)w[i];
    else                    for (int i = 0; i < 4; i++) g_focus[i] = p[i] ? 1 : 0;
}

__global__ void f2h_kernel(const float4* __restrict__ src, uint2* __restrict__ dst, int n4) {
    int i = blockIdx.x * blockDim.x + threadIdx.x;
    if (i < n4) {
        float4 v = src[i];
        dst[i] = make_uint2(packf2(v.x, v.y), packf2(v.z, v.w));
    }
}

// ---------------------------------------------------------------------------
// half GEMM: C(MxN) = A(MxK) @ B(KxN). 128x128x32 tiles, 3-stage cp.async
// pipeline, ldmatrix fragments. 256 thr / 8 warps (4m x 2n).
// ---------------------------------------------------------------------------
#define GS 40
#define BSs 136
#define GABUF (128 * GS)     // halves per A stage
#define GBBUF (32 * BSs)     // halves per B stage
#define GEMM_SMEM (3 * (GABUF + GBBUF) * 2)

__global__ void __launch_bounds__(256, 2) gemm_h(
    int M, int N, int K,
    const __half* __restrict__ A, const __half* __restrict__ B, void* __restrict__ Cv,
    int is_qkv, float qmul, int half_out)
{
    extern __shared__ __half smh[];
    __half* AsB = smh;                 // 3 x GABUF
    __half* BsB = smh + 3 * GABUF;     // 3 x GBBUF

    const int tid  = threadIdx.x;
    const int lane = tid & 31;
    const int w    = tid >> 5;
    const int wm   = (w >> 1) * 32;
    const int wn   = (w & 1) * 64;
    const int brow = blockIdx.y * 128;
    const int bcol = blockIdx.x * 128;

    if (is_qkv && (bcol + 128 <= 1024) && g_focus[brow >> 11]) return;

    const uint32_t as_u = (uint32_t)__cvta_generic_to_shared(AsB);
    const uint32_t bs_u = (uint32_t)__cvta_generic_to_shared(BsB);

    const int rA = ((lane >> 3) & 1) * 8 + (lane & 7);
    const int cA = (lane >> 4) * 8;
    const uint32_t a_frag = as_u + ((wm + rA) * GS + cA) * 2;
    const uint32_t b_frag = bs_u + (rA * BSs + wn + cA) * 2;

    float acc[2][8][4];
#pragma unroll
    for (int mt = 0; mt < 2; mt++)
#pragma unroll
        for (int nt = 0; nt < 8; nt++)
#pragma unroll
            for (int i = 0; i < 4; i++) acc[mt][nt][i] = 0.f;

    const int nk = K / 32;

    // prologue: stages 0 and 1
#pragma unroll
    for (int st = 0; st < 2; st++) {
#pragma unroll
        for (int it = 0; it < 2; it++) {
            int lin = tid + it * 256;
            int r = lin >> 2, c = (lin & 3) * 8;
            cpa16(AsB + st * GABUF + r * GS + c, A + (size_t)(brow + r) * K + st * 32 + c);
            int rb = lin >> 4, cb = (lin & 15) * 8;
            cpa16(BsB + st * GBBUF + rb * BSs + cb, B + (size_t)(st * 32 + rb) * N + bcol + cb);
        }
        CP_COMMIT();
    }
    CP_WAIT1();
    __syncthreads();

    for (int kt = 0; kt < nk; kt++) {
        const int p = kt % 3;

        // prefetch kt+2 into slot (kt+2)%3
        if (kt + 2 < nk) {
            const int pn  = (kt + 2) % 3;
            const int k0n = (kt + 2) * 32;
#pragma unroll
            for (int it = 0; it < 2; it++) {
                int lin = tid + it * 256;
                int r = lin >> 2, c = (lin & 3) * 8;
                cpa16(AsB + pn * GABUF + r * GS + c, A + (size_t)(brow + r) * K + k0n + c);
                int rb = lin >> 4, cb = (lin & 15) * 8;
                cpa16(BsB + pn * GBBUF + rb * BSs + cb, B + (size_t)(k0n + rb) * N + bcol + cb);
            }
        }
        CP_COMMIT();

        const uint32_t af_b = a_frag + p * (GABUF * 2);
        const uint32_t bf_b = b_frag + p * (GBBUF * 2);
#pragma unroll
        for (int kc = 0; kc < 2; kc++) {
            uint32_t af[2][4];
            ldsm4(af[0][0], af[0][1], af[0][2], af[0][3], af_b + kc * 32);
            ldsm4(af[1][0], af[1][1], af[1][2], af[1][3], af_b + kc * 32 + 16 * GS * 2);
            const uint32_t bk = bf_b + kc * (16 * BSs * 2);
#pragma unroll
            for (int ntp = 0; ntp < 4; ntp++) {
                uint32_t b0, b1, b2, b3;
                ldsm4t(b0, b1, b2, b3, bk + ntp * 32);
                mma16(acc[0][2 * ntp],     af[0], b0, b1);
                mma16(acc[0][2 * ntp + 1], af[0], b2, b3);
                mma16(acc[1][2 * ntp],     af[1], b0, b1);
                mma16(acc[1][2 * ntp + 1], af[1], b2, b3);
            }
        }
        CP_WAIT1();
        __syncthreads();
    }

    const float mul = (is_qkv && bcol < 512) ? qmul : 1.0f;
    if (half_out) {
        __half* C = (__half*)Cv;
#pragma unroll
        for (int mt = 0; mt < 2; mt++)
#pragma unroll
            for (int nt = 0; nt < 8; nt++) {
                int r = brow + wm + mt * 16 + (lane >> 2);
                int c = bcol + wn + nt * 8 + (lane & 3) * 2;
                *(uint32_t*)(C + (size_t)r * N + c) =
                    packf2(acc[mt][nt][0] * mul, acc[mt][nt][1] * mul);
                *(uint32_t*)(C + (size_t)(r + 8) * N + c) =
                    packf2(acc[mt][nt][2] * mul, acc[mt][nt][3] * mul);
            }
    } else {
        float* C = (float*)Cv;
#pragma unroll
        for (int mt = 0; mt < 2; mt++)
#pragma unroll
            for (int nt = 0; nt < 8; nt++) {
                int r = brow + wm + mt * 16 + (lane >> 2);
                int c = bcol + wn + nt * 8 + (lane & 3) * 2;
                *(float2*)(C + (size_t)r * N + c)       = make_float2(acc[mt][nt][0], acc[mt][nt][1]);
                *(float2*)(C + (size_t)(r + 8) * N + c) = make_float2(acc[mt][nt][2], acc[mt][nt][3]);
            }
    }
}

// ---------------------------------------------------------------------------
// Flash attention. 3-stage cp.async pipeline for K/V; ldmatrix fragments;
// ones column in V -> PV mma accumulates softmax denominator; base-2 softmax.
// Block = 64 q rows of (b,h), 128 thr / 4 warps.
// ---------------------------------------------------------------------------
#define FS 72
#define FT (64 * FS)                  // halves per tile
#define FLASH_SMEM (7 * FT * 2)       // Q + 3K + 3V

__global__ void __launch_bounds__(128, 3) flash_h(
    const __half* __restrict__ qkv, const float* __restrict__ pos_bias,
    __half* __restrict__ O)
{
    const int qt = blockIdx.x, h = blockIdx.y, b = blockIdx.z;
    const int tid = threadIdx.x, lane = tid & 31, w = tid >> 5;
    const int q0 = qt * 64;

    if (g_focus[b]) {
#pragma unroll
        for (int it = 0; it < 4; it++) {
            int lin = tid + it * 128;
            int r = lin >> 3, cs = (lin & 7) * 8;
            const uint4 v = *(const uint4*)(qkv + (size_t)(b * Nn + q0 + r) * 1536
                                            + 1024 + h * DHn + cs);
            *(uint4*)(O + (size_t)(b * Nn + q0 + r) * HIDn + h * DHn + cs) = v;
        }
        return;
    }

    extern __shared__ __half smh[];
    __half* Qs  = smh;                 // 64 x 72
    __half* KsB = smh + FT;            // 3 x (64 x 72)  [key][d]
    __half* VsB = smh + 4 * FT;        // 3 x (64 x 72)  [key][d], col 64 = ones

    const size_t bN = (size_t)b * Nn;

    const uint32_t qs_u = (uint32_t)__cvta_generic_to_shared(Qs);
    const uint32_t ks_u = (uint32_t)__cvta_generic_to_shared(KsB);
    const uint32_t vs_u = (uint32_t)__cvta_generic_to_shared(VsB);

    // ---- prologue: Q + K0/V0 (group 0), K1/V1 (group 1) ----
#pragma unroll
    for (int it = 0; it < 4; it++) {
        int lin = tid + it * 128;
        int r = lin >> 3, c = (lin & 7) * 8;
        cpa16(Qs  + r * FS + c, qkv + (bN + q0 + r) * 1536 + h * DHn + c);
        cpa16(KsB + r * FS + c, qkv + (bN + r) * 1536 + 512 + h * DHn + c);
        cpa16(VsB + r * FS + c, qkv + (bN + r) * 1536 + 1024 + h * DHn + c);
    }
    CP_COMMIT();
#pragma unroll
    for (int it = 0; it < 4; it++) {
        int lin = tid + it * 128;
        int r = lin >> 3, c = (lin & 7) * 8;
        cpa16(KsB + FT + r * FS + c, qkv + (bN + 64 + r) * 1536 + 512 + h * DHn + c);
        cpa16(VsB + FT + r * FS + c, qkv + (bN + 64 + r) * 1536 + 1024 + h * DHn + c);
    }
    CP_COMMIT();
    // ones column (col 64 = 1, 65..71 = 0) for all 3 V buffers
    {
        uint4 ones = make_uint4(0x00003C00u, 0u, 0u, 0u);
#pragma unroll
        for (int it = 0; it < 2; it++) {
            int lin = tid + it * 128;
            if (lin < 192) {
                int buf = lin >> 6, r = lin & 63;
                *(uint4*)(VsB + buf * FT + r * FS + 64) = ones;
            }
        }
    }
    CP_WAIT1();
    __syncthreads();

    // lane constants
    const int rA = ((lane >> 3) & 1) * 8 + (lane & 7);
    const int cA = (lane >> 4) * 8;
    const int rB = (lane >> 4) * 8 + (lane & 7);
    const int cB = ((lane >> 3) & 1) * 8;

    // Q fragments (A operand)
    uint32_t aq[4][4];
    {
        uint32_t qf = qs_u + ((w * 16 + rA) * FS + cA) * 2;
#pragma unroll
        for (int kc = 0; kc < 4; kc++)
            ldsm4(aq[kc][0], aq[kc][1], aq[kc][2], aq[kc][3], qf + kc * 32);
    }

    const uint32_t k_frag = ks_u + (rB * FS + cB) * 2;
    const uint32_t v_frag = vs_u + (rA * FS + cA) * 2;
    const uint32_t l_frag = vs_u + (rA * FS + 64) * 2;

    float o[9][4];
#pragma unroll
    for (int nt = 0; nt < 9; nt++)
#pragma unroll
        for (int i = 0; i < 4; i++) o[nt][i] = 0.f;
    float m0 = -1e30f, m1 = -1e30f;

    const float* pbbase = pos_bias + ((size_t)h * Nn + (q0 + w * 16 + (lane >> 2))) * Nn
                          + 2 * (lane & 3);

    for (int kt = 0; kt < Nn / 64; kt++) {
        const int p  = kt % 3;
        const int k0 = kt * 64;

        // prefetch kt+2 into slot (kt+2)%3  (readers of that slot done: end-of-prev-iter sync)
        if (kt + 2 < Nn / 64) {
            const int pn = (kt + 2) % 3;
            const int kn = k0 + 128;
#pragma unroll
            for (int it = 0; it < 4; it++) {
                int lin = tid + it * 128;
                int r = lin >> 3, c = (lin & 7) * 8;
                cpa16(KsB + pn * FT + r * FS + c,
                      qkv + (bN + kn + r) * 1536 + 512 + h * DHn + c);
                cpa16(VsB + pn * FT + r * FS + c,
                      qkv + (bN + kn + r) * 1536 + 1024 + h * DHn + c);
            }
        }
        CP_COMMIT();

        // bias loads early (cover LDG latency with QK mma)
        const float* pb0 = pbbase + k0;
        const float* pb1 = pb0 + 8 * Nn;
        float2 x0r[8], x1r[8];
#pragma unroll
        for (int nt = 0; nt < 8; nt++) {
            x0r[nt] = *(const float2*)(pb0 + nt * 8);
            x1r[nt] = *(const float2*)(pb1 + nt * 8);
        }

        // S = Q @ K^T
        float s[8][4];
#pragma unroll
        for (int nt = 0; nt < 8; nt++)
#pragma unroll
            for (int i = 0; i < 4; i++) s[nt][i] = 0.f;
        {
            const uint32_t kb = k_frag + p * (FT * 2);
#pragma unroll
            for (int kc = 0; kc < 4; kc++) {
#pragma unroll
                for (int ntp = 0; ntp < 4; ntp++) {
                    uint32_t b0, b1, b2, b3;
                    ldsm4(b0, b1, b2, b3, kb + ntp * (16 * FS * 2) + kc * 32);
                    mma16(s[2 * ntp],     aq[kc], b0, b1);
                    mma16(s[2 * ntp + 1], aq[kc], b2, b3);
                }
            }
        }

        // + bias * log2e; online max
#pragma unroll
        for (int nt = 0; nt < 8; nt++) {
            s[nt][0] = fmaf(x0r[nt].x, L2E, s[nt][0]);
            s[nt][1] = fmaf(x0r[nt].y, L2E, s[nt][1]);
            s[nt][2] = fmaf(x1r[nt].x, L2E, s[nt][2]);
            s[nt][3] = fmaf(x1r[nt].y, L2E, s[nt][3]);
        }
        float rmax0 = -1e30f, rmax1 = -1e30f;
#pragma unroll
        for (int nt = 0; nt < 8; nt++) {
            rmax0 = fmaxf(rmax0, fmaxf(s[nt][0], s[nt][1]));
            rmax1 = fmaxf(rmax1, fmaxf(s[nt][2], s[nt][3]));
        }
#pragma unroll
        for (int off = 1; off <= 2; off <<= 1) {
            rmax0 = fmaxf(rmax0, __shfl_xor_sync(0xffffffffu, rmax0, off));
            rmax1 = fmaxf(rmax1, __shfl_xor_sync(0xffffffffu, rmax1, off));
        }
        float mn0 = fmaxf(m0, rmax0), mn1 = fmaxf(m1, rmax1);
        float corr0 = ex2f(m0 - mn0), corr1 = ex2f(m1 - mn1);
        m0 = mn0; m1 = mn1;
#pragma unroll
        for (int nt = 0; nt < 9; nt++) {
            o[nt][0] *= corr0; o[nt][1] *= corr0;
            o[nt][2] *= corr1; o[nt][3] *= corr1;
        }

        // P = ex2(s - mn) in half2 (A-operand layout)
        uint32_t pa[4][4];
#pragma unroll
        for (int kc = 0; kc < 4; kc++) {
            pa[kc][0] = ex2h2(s[2 * kc][0]     - mn0, s[2 * kc][1]     - mn0);
            pa[kc][1] = ex2h2(s[2 * kc][2]     - mn1, s[2 * kc][3]     - mn1);
            pa[kc][2] = ex2h2(s[2 * kc + 1][0] - mn0, s[2 * kc + 1][1] - mn0);
            pa[kc][3] = ex2h2(s[2 * kc + 1][2] - mn1, s[2 * kc + 1][3] - mn1);
        }

        // O += P @ V  (trans ldmatrix); l via ones column
        {
            const uint32_t vb = v_frag + p * (FT * 2);
            const uint32_t lb = l_frag + p * (FT * 2);
#pragma unroll
            for (int kc = 0; kc < 4; kc++) {
                const uint32_t vk = vb + kc * (16 * FS * 2);
#pragma unroll
                for (int ntp = 0; ntp < 4; ntp++) {
                    uint32_t b0, b1, b2, b3;
                    ldsm4t(b0, b1, b2, b3, vk + ntp * 32);
                    mma16(o[2 * ntp],     pa[kc], b0, b1);
                    mma16(o[2 * ntp + 1], pa[kc], b2, b3);
                }
                uint32_t lb0, lb1;
                ldsm2t(lb0, lb1, lb + kc * (16 * FS * 2));
                mma16(o[8], pa[kc], lb0, lb1);
            }
        }

        CP_WAIT1();
        __syncthreads();
    }

    // l from ones column
    float l0 = __shfl_sync(0xffffffffu, o[8][0], lane & 28);
    float l1 = __shfl_sync(0xffffffffu, o[8][2], lane & 28);
    float inv0 = 1.f / l0, inv1 = 1.f / l1;

    int gr = b * Nn + q0 + w * 16 + (lane >> 2);
    __half* op = O + (size_t)gr * HIDn + h * DHn + 2 * (lane & 3);
#pragma unroll
    for (int nt = 0; nt < 8; nt++) {
        *(uint32_t*)(op + nt * 8)            = packf2(o[nt][0] * inv0, o[nt][1] * inv0);
        *(uint32_t*)(op + 8 * HIDn + nt * 8) = packf2(o[nt][2] * inv1, o[nt][3] * inv1);
    }
}

// ---------------------------------------------------------------------------
extern "C" void kernel_launch(void* const* d_in, const int* in_sizes, int n_in,
                              void* d_out, int out_size)
{
    const float*         x        = (const float*)d_in[0];
    const float*         pos_bias = (const float*)d_in[1];
    const unsigned char* maskp    = (const unsigned char*)d_in[2];
    const float*         w_qkv    = (const float*)d_in[3];
    const float*         w_out    = (const float*)d_in[4];
    float*               out      = (float*)d_out;

    __half *xh, *wqkvh, *wouth, *qkvh, *oh;
    cudaGetSymbolAddress((void**)&xh,    g_xh);
    cudaGetSymbolAddress((void**)&wqkvh, g_wqkvh);
    cudaGetSymbolAddress((void**)&wouth, g_wouth);
    cudaGetSymbolAddress((void**)&qkvh,  g_qkvh);
    cudaGetSymbolAddress((void**)&oh,    g_oh);

    cudaFuncSetAttribute(gemm_h,  cudaFuncAttributeMaxDynamicSharedMemorySize, GEMM_SMEM);
    cudaFuncSetAttribute(flash_h, cudaFuncAttributeMaxDynamicSharedMemorySize, FLASH_SMEM);

    decode_mask_kernel<<<1, 1>>>(maskp);

    f2h_kernel<<<(Bn * Nn * 512 / 4 + 255) / 256, 256>>>((const float4*)x, (uint2*)xh,
                                                         Bn * Nn * 512 / 4);
    f2h_kernel<<<(512 * 1536 / 4 + 255) / 256, 256>>>((const float4*)w_qkv, (uint2*)wqkvh,
                                                      512 * 1536 / 4);
    f2h_kernel<<<(512 * 512 / 4 + 255) / 256, 256>>>((const float4*)w_out, (uint2*)wouth,
                                                     512 * 512 / 4);

    // qkv = x @ w_qkv  (half out; q cols pre-scaled; focus q/k skip)
    gemm_h<<<dim3(12, 64), 256, GEMM_SMEM>>>(8192, 1536, 512, xh, wqkvh, qkvh,
                                             1, QSCALEC, 1);

    // fused flash attention
    flash_h<<<dim3(Nn / 64, HEADSn, Bn), 128, FLASH_SMEM>>>(qkvh, pos_bias, oh);

    // out = O @ w_out (float out)
    gemm_h<<<dim3(4, 64), 256, GEMM_SMEM>>>(8192, 512, 512, oh, wouth, out,
                                            0, 1.0f, 0);
}

// round 8
// speedup vs baseline: 1.0888x; 1.0888x over previous
#include <cuda_runtime.h>
#include <cuda_fp16.h>
#include <stdint.h>

#define Bn    4
#define Nn    2048
#define HEADSn 8
#define DHn   64
#define HIDn  512
#define L2E   1.4426950408889634f
#define QSCALEC (0.125f * 1.4426950408889634f)

// Scratch (device globals; allocation-free rule)
__device__ __half g_xh   [Bn * Nn * 512];
__device__ __half g_wqkvh[512 * 1536];
__device__ __half g_wouth[512 * 512];
__device__ __half g_qkvh [Bn * Nn * 1536];   // q|k|v halves (q pre-scaled)
__device__ __half g_oh   [Bn * Nn * 512];
__device__ int    g_focus[Bn];

// ---------------------------------------------------------------------------
__device__ __forceinline__ float ex2f(float x) {
    float r; asm("ex2.approx.ftz.f32 %0, %1;" : "=f"(r) : "f"(x)); return r;
}
__device__ __forceinline__ uint32_t ex2h2(float a, float b) {
    __half2 h = __floats2half2_rn(a, b);
    uint32_t u = *reinterpret_cast<uint32_t*>(&h);
    asm("ex2.approx.f16x2 %0, %0;" : "+r"(u));
    return u;
}
__device__ __forceinline__ uint32_t packf2(float a, float b) {
    __half2 h = __floats2half2_rn(a, b);
    return *reinterpret_cast<uint32_t*>(&h);
}
__device__ __forceinline__ void mma16(float* d, const uint32_t* a, uint32_t b0, uint32_t b1) {
    asm volatile(
        "mma.sync.aligned.m16n8k16.row.col.f32.f16.f16.f32 "
        "{%0,%1,%2,%3}, {%4,%5,%6,%7}, {%8,%9}, {%0,%1,%2,%3};"
        : "+f"(d[0]), "+f"(d[1]), "+f"(d[2]), "+f"(d[3])
        : "r"(a[0]), "r"(a[1]), "r"(a[2]), "r"(a[3]), "r"(b0), "r"(b1));
}
__device__ __forceinline__ void ldsm4(uint32_t& r0, uint32_t& r1, uint32_t& r2, uint32_t& r3,
                                      uint32_t a) {
    asm volatile("ldmatrix.sync.aligned.m8n8.x4.shared.b16 {%0,%1,%2,%3}, [%4];"
        : "=r"(r0), "=r"(r1), "=r"(r2), "=r"(r3) : "r"(a));
}
__device__ __forceinline__ void ldsm4t(uint32_t& r0, uint32_t& r1, uint32_t& r2, uint32_t& r3,
                                       uint32_t a) {
    asm volatile("ldmatrix.sync.aligned.m8n8.x4.trans.shared.b16 {%0,%1,%2,%3}, [%4];"
        : "=r"(r0), "=r"(r1), "=r"(r2), "=r"(r3) : "r"(a));
}
__device__ __forceinline__ void ldsm2t(uint32_t& r0, uint32_t& r1, uint32_t a) {
    asm volatile("ldmatrix.sync.aligned.m8n8.x2.trans.shared.b16 {%0,%1}, [%2];"
        : "=r"(r0), "=r"(r1) : "r"(a));
}
__device__ __forceinline__ void cpa16(void* s, const void* g) {
    uint32_t sa = (uint32_t)__cvta_generic_to_shared(s);
    asm volatile("cp.async.ca.shared.global [%0], [%1], 16;" :: "r"(sa), "l"(g));
}
#define CP_COMMIT() asm volatile("cp.async.commit_group;")
#define CP_WAIT0()  asm volatile("cp.async.wait_group 0;")

// ---------------------------------------------------------------------------
__global__ void decode_mask_kernel(const unsigned char* __restrict__ p) {
    unsigned int w[4];
#pragma unroll
    for (int i = 0; i < 4; i++) w[i] = ((const unsigned int*)p)[i];
    bool allF = true, allI = true, anyNZ = false;
#pragma unroll
    for (int i = 0; i < 4; i++) {
        if (w[i] != 0u) anyNZ = true;
        if (w[i] != 0u && w[i] != 0x3F800000u) allF = false;
        if (w[i] > 1u) allI = false;
    }
    if (anyNZ && allF)      for (int i = 0; i < 4; i++) g_focus[i] = (w[i] == 0x3F800000u);
    else if (allI)          for (int i = 0; i < 4; i++) g_focus[i] = (int)w[i];
    else                    for (int i = 0; i < 4; i++) g_focus[i] = p[i] ? 1 : 0;
}

// Fused fp32->fp16 convert of x, w_qkv, w_out (one launch)
__global__ void f2h3_kernel(const float4* __restrict__ s0, uint2* __restrict__ d0, int n0,
                            const float4* __restrict__ s1, uint2* __restrict__ d1, int n1,
                            const float4* __restrict__ s2, uint2* __restrict__ d2, int n2) {
    int i = blockIdx.x * blockDim.x + threadIdx.x;
    const float4* s; uint2* d; int j;
    if (i < n0)           { s = s0; d = d0; j = i; }
    else if (i < n0 + n1) { s = s1; d = d1; j = i - n0; }
    else if (i < n0 + n1 + n2) { s = s2; d = d2; j = i - n0 - n1; }
    else return;
    float4 v = s[j];
    d[j] = make_uint2(packf2(v.x, v.y), packf2(v.z, v.w));
}

// ---------------------------------------------------------------------------
// half GEMM: C(MxN) = A(MxK) @ B(KxN). 128x128x32 tiles, double-buffered,
// all-cp.async loads, ldmatrix fragments. 256 thr / 8 warps (4m x 2n).
// ---------------------------------------------------------------------------
#define GS 40
#define BSs 136
#define GABUF (128 * GS)     // halves
#define GBBUF (32 * BSs)     // halves
#define GEMM_SMEM ((2 * GABUF + 2 * GBBUF) * 2)

__global__ void __launch_bounds__(256, 2) gemm_h(
    int M, int N, int K,
    const __half* __restrict__ A, const __half* __restrict__ B, void* __restrict__ Cv,
    int is_qkv, float qmul, int half_out)
{
    extern __shared__ __half smh[];
    __half* AsB = smh;
    __half* BsB = smh + 2 * GABUF;

    const int tid  = threadIdx.x;
    const int lane = tid & 31;
    const int w    = tid >> 5;
    const int wm   = (w >> 1) * 32;
    const int wn   = (w & 1) * 64;
    const int brow = blockIdx.y * 128;
    const int bcol = blockIdx.x * 128;

    if (is_qkv && (bcol + 128 <= 1024) && g_focus[brow >> 11]) return;

    const uint32_t as_u = (uint32_t)__cvta_generic_to_shared(AsB);
    const uint32_t bs_u = (uint32_t)__cvta_generic_to_shared(BsB);

    const int rA = ((lane >> 3) & 1) * 8 + (lane & 7);
    const int cA = (lane >> 4) * 8;
    const uint32_t a_frag = as_u + ((wm + rA) * GS + cA) * 2;
    const uint32_t b_frag = bs_u + (rA * BSs + wn + cA) * 2;

    float acc[2][8][4];
#pragma unroll
    for (int mt = 0; mt < 2; mt++)
#pragma unroll
        for (int nt = 0; nt < 8; nt++)
#pragma unroll
            for (int i = 0; i < 4; i++) acc[mt][nt][i] = 0.f;

    const int nk = K / 32;

    // prologue: stage 0
#pragma unroll
    for (int it = 0; it < 2; it++) {
        int lin = tid + it * 256;
        int r = lin >> 2, c = (lin & 3) * 8;
        cpa16(AsB + r * GS + c, A + (size_t)(brow + r) * K + c);
        int rb = lin >> 4, cb = (lin & 15) * 8;
        cpa16(BsB + rb * BSs + cb, B + (size_t)rb * N + bcol + cb);
    }
    CP_COMMIT();
    CP_WAIT0();
    __syncthreads();

    for (int kt = 0; kt < nk; kt++) {
        const int p   = kt & 1;
        const int k0n = (kt + 1) * 32;
        const bool more = (kt + 1 < nk);

        if (more) {
#pragma unroll
            for (int it = 0; it < 2; it++) {
                int lin = tid + it * 256;
                int r = lin >> 2, c = (lin & 3) * 8;
                cpa16(AsB + (p ^ 1) * GABUF + r * GS + c,
                      A + (size_t)(brow + r) * K + k0n + c);
                int rb = lin >> 4, cb = (lin & 15) * 8;
                cpa16(BsB + (p ^ 1) * GBBUF + rb * BSs + cb,
                      B + (size_t)(k0n + rb) * N + bcol + cb);
            }
        }
        CP_COMMIT();

        const uint32_t af_b = a_frag + p * (GABUF * 2);
        const uint32_t bf_b = b_frag + p * (GBBUF * 2);
#pragma unroll
        for (int kc = 0; kc < 2; kc++) {
            uint32_t af[2][4];
            ldsm4(af[0][0], af[0][1], af[0][2], af[0][3], af_b + kc * 32);
            ldsm4(af[1][0], af[1][1], af[1][2], af[1][3], af_b + kc * 32 + 16 * GS * 2);
            const uint32_t bk = bf_b + kc * (16 * BSs * 2);
#pragma unroll
            for (int ntp = 0; ntp < 4; ntp++) {
                uint32_t b0, b1, b2, b3;
                ldsm4t(b0, b1, b2, b3, bk + ntp * 32);
                mma16(acc[0][2 * ntp],     af[0], b0, b1);
                mma16(acc[0][2 * ntp + 1], af[0], b2, b3);
                mma16(acc[1][2 * ntp],     af[1], b0, b1);
                mma16(acc[1][2 * ntp + 1], af[1], b2, b3);
            }
        }
        CP_WAIT0();
        __syncthreads();
    }

    const float mul = (is_qkv && bcol < 512) ? qmul : 1.0f;
    if (half_out) {
        __half* C = (__half*)Cv;
#pragma unroll
        for (int mt = 0; mt < 2; mt++)
#pragma unroll
            for (int nt = 0; nt < 8; nt++) {
                int r = brow + wm + mt * 16 + (lane >> 2);
                int c = bcol + wn + nt * 8 + (lane & 3) * 2;
                *(uint32_t*)(C + (size_t)r * N + c) =
                    packf2(acc[mt][nt][0] * mul, acc[mt][nt][1] * mul);
                *(uint32_t*)(C + (size_t)(r + 8) * N + c) =
                    packf2(acc[mt][nt][2] * mul, acc[mt][nt][3] * mul);
            }
    } else {
        float* C = (float*)Cv;
#pragma unroll
        for (int mt = 0; mt < 2; mt++)
#pragma unroll
            for (int nt = 0; nt < 8; nt++) {
                int r = brow + wm + mt * 16 + (lane >> 2);
                int c = bcol + wn + nt * 8 + (lane & 3) * 2;
                *(float2*)(C + (size_t)r * N + c)       = make_float2(acc[mt][nt][0], acc[mt][nt][1]);
                *(float2*)(C + (size_t)(r + 8) * N + c) = make_float2(acc[mt][nt][2], acc[mt][nt][3]);
            }
    }
}

// ---------------------------------------------------------------------------
// Flash attention (R6 structure). Grid: (batch, head, qtile) with batch the
// FASTEST dim so all batches of one (h,qt) are schedule-adjacent -> the shared
// pos_bias tile is read from DRAM once and L2-hits for the other batches.
// ---------------------------------------------------------------------------
#define FS 72
#define FT (64 * FS)                 // halves per tile
#define FLASH_SMEM (5 * FT * 2)      // Qs + 2K + 2V

__global__ void __launch_bounds__(128, 3) flash_h(
    const __half* __restrict__ qkv, const float* __restrict__ pos_bias,
    __half* __restrict__ O)
{
    const int b = blockIdx.x, h = blockIdx.y, qt = blockIdx.z;
    const int tid = threadIdx.x, lane = tid & 31, w = tid >> 5;
    const int q0 = qt * 64;

    if (g_focus[b]) {
#pragma unroll
        for (int it = 0; it < 4; it++) {
            int lin = tid + it * 128;
            int r = lin >> 3, cs = (lin & 7) * 8;
            const uint4 v = *(const uint4*)(qkv + (size_t)(b * Nn + q0 + r) * 1536
                                            + 1024 + h * DHn + cs);
            *(uint4*)(O + (size_t)(b * Nn + q0 + r) * HIDn + h * DHn + cs) = v;
        }
        return;
    }

    extern __shared__ __half smh[];
    __half* Qs  = smh;               // 64 x 72
    __half* KsB = smh + FT;          // 2 x (64 x 72)  [key][d]
    __half* VsB = smh + 3 * FT;      // 2 x (64 x 72)  [key][d], col 64 = ones

    const size_t bN = (size_t)b * Nn;

    const uint32_t qs_u = (uint32_t)__cvta_generic_to_shared(Qs);
    const uint32_t ks_u = (uint32_t)__cvta_generic_to_shared(KsB);
    const uint32_t vs_u = (uint32_t)__cvta_generic_to_shared(VsB);

    // ---- prologue: Q, K0, V0 via cp.async ----
#pragma unroll
    for (int it = 0; it < 4; it++) {
        int lin = tid + it * 128;
        int r = lin >> 3, c = (lin & 7) * 8;
        cpa16(Qs  + r * FS + c, qkv + (bN + q0 + r) * 1536 + h * DHn + c);
        cpa16(KsB + r * FS + c, qkv + (bN + r) * 1536 + 512 + h * DHn + c);
        cpa16(VsB + r * FS + c, qkv + (bN + r) * 1536 + 1024 + h * DHn + c);
    }
    CP_COMMIT();
    // ones column (col 64 = 1, 65..71 = 0) for both V buffers
    {
        uint4 ones = make_uint4(0x00003C00u, 0u, 0u, 0u);
        int buf = tid >> 6, r = tid & 63;
        *(uint4*)(VsB + buf * FT + r * FS + 64) = ones;
    }
    CP_WAIT0();
    __syncthreads();

    // lane constants
    const int rA = ((lane >> 3) & 1) * 8 + (lane & 7);   // A-type / trans-B row
    const int cA = (lane >> 4) * 8;                      // A-type / trans-B col
    const int rB = (lane >> 4) * 8 + (lane & 7);         // non-trans B row
    const int cB = ((lane >> 3) & 1) * 8;                // non-trans B col

    // Q fragments (A operand) via ldmatrix
    uint32_t aq[4][4];
    {
        uint32_t qf = qs_u + ((w * 16 + rA) * FS + cA) * 2;
#pragma unroll
        for (int kc = 0; kc < 4; kc++)
            ldsm4(aq[kc][0], aq[kc][1], aq[kc][2], aq[kc][3], qf + kc * 32);
    }

    const uint32_t k_frag = ks_u + (rB * FS + cB) * 2;
    const uint32_t v_frag = vs_u + (rA * FS + cA) * 2;
    const uint32_t l_frag = vs_u + (rA * FS + 64) * 2;

    float o[9][4];
#pragma unroll
    for (int nt = 0; nt < 9; nt++)
#pragma unroll
        for (int i = 0; i < 4; i++) o[nt][i] = 0.f;
    float m0 = -1e30f, m1 = -1e30f;

    const float* pbbase = pos_bias + ((size_t)h * Nn + (q0 + w * 16 + (lane >> 2))) * Nn
                          + 2 * (lane & 3);

    for (int kt = 0; kt < Nn / 64; kt++) {
        const int p  = kt & 1;
        const int k0 = kt * 64;
        const bool more = (kt + 1 < Nn / 64);

        // prefetch next K,V tiles
        if (more) {
            const int kn = k0 + 64;
#pragma unroll
            for (int it = 0; it < 4; it++) {
                int lin = tid + it * 128;
                int r = lin >> 3, c = (lin & 7) * 8;
                cpa16(KsB + (p ^ 1) * FT + r * FS + c,
                      qkv + (bN + kn + r) * 1536 + 512 + h * DHn + c);
                cpa16(VsB + (p ^ 1) * FT + r * FS + c,
                      qkv + (bN + kn + r) * 1536 + 1024 + h * DHn + c);
            }
        }
        CP_COMMIT();

        // bias loads early (cover LDG latency with QK mma)
        const float* pb0 = pbbase + k0;
        const float* pb1 = pb0 + 8 * Nn;
        float2 x0r[8], x1r[8];
#pragma unroll
        for (int nt = 0; nt < 8; nt++) {
            x0r[nt] = *(const float2*)(pb0 + nt * 8);
            x1r[nt] = *(const float2*)(pb1 + nt * 8);
        }

        // S = Q @ K^T
        float s[8][4];
#pragma unroll
        for (int nt = 0; nt < 8; nt++)
#pragma unroll
            for (int i = 0; i < 4; i++) s[nt][i] = 0.f;
        {
            const uint32_t kb = k_frag + p * (FT * 2);
#pragma unroll
            for (int kc = 0; kc < 4; kc++) {
#pragma unroll
                for (int ntp = 0; ntp < 4; ntp++) {
                    uint32_t b0, b1, b2, b3;
                    ldsm4(b0, b1, b2, b3, kb + ntp * (16 * FS * 2) + kc * 32);
                    mma16(s[2 * ntp],     aq[kc], b0, b1);
                    mma16(s[2 * ntp + 1], aq[kc], b2, b3);
                }
            }
        }

        // + bias * log2e; online max
#pragma unroll
        for (int nt = 0; nt < 8; nt++) {
            s[nt][0] = fmaf(x0r[nt].x, L2E, s[nt][0]);
            s[nt][1] = fmaf(x0r[nt].y, L2E, s[nt][1]);
            s[nt][2] = fmaf(x1r[nt].x, L2E, s[nt][2]);
            s[nt][3] = fmaf(x1r[nt].y, L2E, s[nt][3]);
        }
        float rmax0 = -1e30f, rmax1 = -1e30f;
#pragma unroll
        for (int nt = 0; nt < 8; nt++) {
            rmax0 = fmaxf(rmax0, fmaxf(s[nt][0], s[nt][1]));
            rmax1 = fmaxf(rmax1, fmaxf(s[nt][2], s[nt][3]));
        }
#pragma unroll
        for (int off = 1; off <= 2; off <<= 1) {
            rmax0 = fmaxf(rmax0, __shfl_xor_sync(0xffffffffu, rmax0, off));
            rmax1 = fmaxf(rmax1, __shfl_xor_sync(0xffffffffu, rmax1, off));
        }
        float mn0 = fmaxf(m0, rmax0), mn1 = fmaxf(m1, rmax1);
        float corr0 = ex2f(m0 - mn0), corr1 = ex2f(m1 - mn1);
        m0 = mn0; m1 = mn1;
#pragma unroll
        for (int nt = 0; nt < 9; nt++) {
            o[nt][0] *= corr0; o[nt][1] *= corr0;
            o[nt][2] *= corr1; o[nt][3] *= corr1;
        }

        // P = ex2(s - mn) in half2 (A-operand layout)
        uint32_t pa[4][4];
#pragma unroll
        for (int kc = 0; kc < 4; kc++) {
            pa[kc][0] = ex2h2(s[2 * kc][0]     - mn0, s[2 * kc][1]     - mn0);
            pa[kc][1] = ex2h2(s[2 * kc][2]     - mn1, s[2 * kc][3]     - mn1);
            pa[kc][2] = ex2h2(s[2 * kc + 1][0] - mn0, s[2 * kc + 1][1] - mn0);
            pa[kc][3] = ex2h2(s[2 * kc + 1][2] - mn1, s[2 * kc + 1][3] - mn1);
        }

        // O += P @ V  (trans ldmatrix from [key][d]); l via ones column
        {
            const uint32_t vb = v_frag + p * (FT * 2);
            const uint32_t lb = l_frag + p * (FT * 2);
#pragma unroll
            for (int kc = 0; kc < 4; kc++) {
                const uint32_t vk = vb + kc * (16 * FS * 2);
#pragma unroll
                for (int ntp = 0; ntp < 4; ntp++) {
                    uint32_t b0, b1, b2, b3;
                    ldsm4t(b0, b1, b2, b3, vk + ntp * 32);
                    mma16(o[2 * ntp],     pa[kc], b0, b1);
                    mma16(o[2 * ntp + 1], pa[kc], b2, b3);
                }
                uint32_t lb0, lb1;
                ldsm2t(lb0, lb1, lb + kc * (16 * FS * 2));
                mma16(o[8], pa[kc], lb0, lb1);
            }
        }
        CP_WAIT0();
        __syncthreads();
    }

    // l from ones column
    float l0 = __shfl_sync(0xffffffffu, o[8][0], lane & 28);
    float l1 = __shfl_sync(0xffffffffu, o[8][2], lane & 28);
    float inv0 = 1.f / l0, inv1 = 1.f / l1;

    int gr = b * Nn + q0 + w * 16 + (lane >> 2);
    __half* op = O + (size_t)gr * HIDn + h * DHn + 2 * (lane & 3);
#pragma unroll
    for (int nt = 0; nt < 8; nt++) {
        *(uint32_t*)(op + nt * 8)            = packf2(o[nt][0] * inv0, o[nt][1] * inv0);
        *(uint32_t*)(op + 8 * HIDn + nt * 8) = packf2(o[nt][2] * inv1, o[nt][3] * inv1);
    }
}

// ---------------------------------------------------------------------------
extern "C" void kernel_launch(void* const* d_in, const int* in_sizes, int n_in,
                              void* d_out, int out_size)
{
    const float*         x        = (const float*)d_in[0];
    const float*         pos_bias = (const float*)d_in[1];
    const unsigned char* maskp    = (const unsigned char*)d_in[2];
    const float*         w_qkv    = (const float*)d_in[3];
    const float*         w_out    = (const float*)d_in[4];
    float*               out      = (float*)d_out;

    __half *xh, *wqkvh, *wouth, *qkvh, *oh;
    cudaGetSymbolAddress((void**)&xh,    g_xh);
    cudaGetSymbolAddress((void**)&wqkvh, g_wqkvh);
    cudaGetSymbolAddress((void**)&wouth, g_wouth);
    cudaGetSymbolAddress((void**)&qkvh,  g_qkvh);
    cudaGetSymbolAddress((void**)&oh,    g_oh);

    cudaFuncSetAttribute(gemm_h,  cudaFuncAttributeMaxDynamicSharedMemorySize, GEMM_SMEM);
    cudaFuncSetAttribute(flash_h, cudaFuncAttributeMaxDynamicSharedMemorySize, FLASH_SMEM);

    decode_mask_kernel<<<1, 1>>>(maskp);

    const int n0 = Bn * Nn * 512 / 4, n1 = 512 * 1536 / 4, n2 = 512 * 512 / 4;
    f2h3_kernel<<<(n0 + n1 + n2 + 255) / 256, 256>>>(
        (const float4*)x, (uint2*)xh, n0,
        (const float4*)w_qkv, (uint2*)wqkvh, n1,
        (const float4*)w_out, (uint2*)wouth, n2);

    // qkv = x @ w_qkv  (half out; q cols pre-scaled; focus q/k skip)
    gemm_h<<<dim3(12, 64), 256, GEMM_SMEM>>>(8192, 1536, 512, xh, wqkvh, qkvh,
                                             1, QSCALEC, 1);

    // fused flash attention (batch = fastest grid dim for bias L2 dedup)
    flash_h<<<dim3(Bn, HEADSn, Nn / 64), 128, FLASH_SMEM>>>(qkvh, pos_bias, oh);

    // out = O @ w_out (float out)
    gemm_h<<<dim3(4, 64), 256, GEMM_SMEM>>>(8192, 512, 512, oh, wouth, out,
                                            0, 1.0f, 0);
}